// round 1
// baseline (speedup 1.0000x reference)
#include <cuda_runtime.h>
#include <math.h>

#define BB 1024
#define CC 64
#define DD 256
#define NN 512
#define K2 (2*DD)

// scratch for sparse activation (indices/values of winners per row)
__device__ int   g_idx[BB*CC*32];
__device__ float g_val[BB*CC*32];
__device__ int   g_cnt[BB*CC];

// ---------------------------------------------------------------------------
// Kernel 1: drive[b,c,n] = x_in[b,:]·W_ff[c,:,n] + 0.3*x_ctx[b,:]·W_ctx[c,:,n] + bias[c,n]
// Treated as one GEMM per c with K=512 (stacked halves). 128x128 tile, 8x8/thread.
// ---------------------------------------------------------------------------
__global__ __launch_bounds__(256) void drive_gemm(
    const float* __restrict__ x_in, const float* __restrict__ x_ctx,
    const float* __restrict__ Wff,  const float* __restrict__ Wctx,
    const float* __restrict__ bias, float* __restrict__ act)
{
    const int BM = 128, BN = 128, BK = 16;
    __shared__ float As[BK][BM];
    __shared__ float Bs[BK][BN];

    int c  = blockIdx.z;
    int m0 = blockIdx.y * BM;
    int n0 = blockIdx.x * BN;
    int tid = threadIdx.x;
    int tx = tid % 16, ty = tid / 16;

    float acc[8][8];
    #pragma unroll
    for (int i = 0; i < 8; i++)
        #pragma unroll
        for (int j = 0; j < 8; j++) acc[i][j] = 0.f;

    const float* WffC  = Wff  + (size_t)c * DD * NN;
    const float* WctxC = Wctx + (size_t)c * DD * NN;

    for (int k0 = 0; k0 < K2; k0 += BK) {
        // ---- load A' tile (128 rows x 16 k) ----
        const float* asrc  = (k0 < DD) ? (x_in + k0) : (x_ctx + (k0 - DD));
        float        ascale = (k0 < DD) ? 1.0f : 0.3f;
        #pragma unroll
        for (int i = 0; i < 2; i++) {
            int t  = tid + i * 256;       // 0..511 float4 slots (128 rows x 4 f4)
            int m  = t >> 2;
            int kq = (t & 3) << 2;
            float4 v = *reinterpret_cast<const float4*>(asrc + (size_t)(m0 + m) * DD + kq);
            As[kq + 0][m] = v.x * ascale;
            As[kq + 1][m] = v.y * ascale;
            As[kq + 2][m] = v.z * ascale;
            As[kq + 3][m] = v.w * ascale;
        }
        // ---- load B' tile (16 k x 128 n) ----
        const float* wsrc = (k0 < DD) ? (WffC + (size_t)k0 * NN)
                                      : (WctxC + (size_t)(k0 - DD) * NN);
        #pragma unroll
        for (int i = 0; i < 2; i++) {
            int t  = tid + i * 256;       // 16 rows x 32 f4
            int kk = t >> 5;
            int nq = (t & 31) << 2;
            float4 v = *reinterpret_cast<const float4*>(wsrc + (size_t)kk * NN + n0 + nq);
            *reinterpret_cast<float4*>(&Bs[kk][nq]) = v;
        }
        __syncthreads();

        #pragma unroll
        for (int kk = 0; kk < BK; kk++) {
            float ra[8], rb[8];
            *reinterpret_cast<float4*>(&ra[0]) = *reinterpret_cast<const float4*>(&As[kk][ty * 8]);
            *reinterpret_cast<float4*>(&ra[4]) = *reinterpret_cast<const float4*>(&As[kk][ty * 8 + 4]);
            *reinterpret_cast<float4*>(&rb[0]) = *reinterpret_cast<const float4*>(&Bs[kk][tx * 8]);
            *reinterpret_cast<float4*>(&rb[4]) = *reinterpret_cast<const float4*>(&Bs[kk][tx * 8 + 4]);
            #pragma unroll
            for (int i = 0; i < 8; i++)
                #pragma unroll
                for (int j = 0; j < 8; j++)
                    acc[i][j] = fmaf(ra[i], rb[j], acc[i][j]);
        }
        __syncthreads();
    }

    // epilogue: + bias, store as drive into the activation slot of d_out
    const float* bb = bias + (size_t)c * NN + n0 + tx * 8;
    #pragma unroll
    for (int i = 0; i < 8; i++) {
        int m = m0 + ty * 8 + i;
        float* dst = act + ((size_t)m * CC + c) * NN + n0 + tx * 8;
        #pragma unroll
        for (int j = 0; j < 8; j += 4) {
            float4 o;
            o.x = acc[i][j + 0] + bb[j + 0];
            o.y = acc[i][j + 1] + bb[j + 1];
            o.z = acc[i][j + 2] + bb[j + 2];
            o.w = acc[i][j + 3] + bb[j + 3];
            *reinterpret_cast<float4*>(dst + j) = o;
        }
    }
}

// ---------------------------------------------------------------------------
// Kernel 2: per-row (b,c) k-WTA: boost, top-k threshold via bitonic sort,
// relu*mask, normalize to sum k, write activation in place, compact winners.
// ---------------------------------------------------------------------------
__global__ __launch_bounds__(NN) void topk_norm(
    const float* __restrict__ avg, const int* __restrict__ kptr,
    float* __restrict__ act)
{
    int row = blockIdx.x;       // b*C + c
    int c   = row % CC;
    int n   = threadIdx.x;      // 512 threads

    __shared__ float sb[NN];       // sort buffer
    __shared__ float sboost[NN];
    __shared__ float sdrive[NN];
    __shared__ float warpsum[16];
    __shared__ float ssum;
    __shared__ int   scnt;

    float drive   = act[(size_t)row * NN + n];
    float boost   = log1pf(0.05f / (avg[(size_t)c * NN + n] + 1e-6f));
    float boosted = drive + boost;   // HOMEOSTASIS*100 = 1.0
    sdrive[n] = drive;
    sboost[n] = boosted;
    sb[n]     = boosted;
    if (n == 0) { scnt = 0; }
    __syncthreads();

    // bitonic sort, descending
    for (int size = 2; size <= NN; size <<= 1) {
        for (int stride = size >> 1; stride > 0; stride >>= 1) {
            int partner = n ^ stride;
            if (partner > n) {
                bool desc = ((n & size) == 0);
                float a = sb[n], b = sb[partner];
                bool sw = desc ? (a < b) : (a > b);
                if (sw) { sb[n] = b; sb[partner] = a; }
            }
            __syncthreads();
        }
    }

    int k = *kptr;
    float thr = sb[k - 1];
    bool win = (sboost[n] >= thr);
    float a = win ? fmaxf(sdrive[n], 0.f) : 0.f;

    // block reduce sum(a)
    float s = a;
    #pragma unroll
    for (int off = 16; off > 0; off >>= 1) s += __shfl_down_sync(0xffffffffu, s, off);
    if ((n & 31) == 0) warpsum[n >> 5] = s;
    __syncthreads();
    if (n < 16) {
        float t = warpsum[n];
        #pragma unroll
        for (int off = 8; off > 0; off >>= 1) t += __shfl_down_sync(0xffffu, t, off);
        if (n == 0) ssum = t;
    }
    __syncthreads();

    float scale = (float)k / (ssum + 1e-8f);
    float outv  = a * scale;
    act[(size_t)row * NN + n] = outv;

    if (win) {
        int p = atomicAdd(&scnt, 1);
        if (p < 32) {
            g_idx[(size_t)row * 32 + p] = n;
            g_val[(size_t)row * 32 + p] = outv;
        }
    }
    __syncthreads();
    if (n == 0) g_cnt[row] = (scnt < 32) ? scnt : 32;
}

// ---------------------------------------------------------------------------
// Kernel 3: predictions[b,c,:] = sum_j val_j * W_pred[c, idx_j, :]
//           errors = x_input - predictions.   Sparse: only ~k=24 terms.
// ---------------------------------------------------------------------------
__global__ __launch_bounds__(DD) void pred_err(
    const float* __restrict__ x_in, const float* __restrict__ Wp,
    float* __restrict__ pred, float* __restrict__ err)
{
    int row = blockIdx.x;       // b*C + c
    int c   = row % CC;
    int b   = row / CC;
    int d   = threadIdx.x;      // 256 threads

    __shared__ float vv[32];
    __shared__ int   ii[32];
    __shared__ int   scnt;
    if (d == 0) scnt = g_cnt[row];
    if (d < 32) {
        vv[d] = g_val[(size_t)row * 32 + d];
        ii[d] = g_idx[(size_t)row * 32 + d];
    }
    __syncthreads();

    int cnt = scnt;
    float acc = 0.f;
    const float* WpC = Wp + (size_t)c * NN * DD;
    for (int j = 0; j < cnt; j++)
        acc = fmaf(vv[j], WpC[(size_t)ii[j] * DD + d], acc);

    pred[(size_t)row * DD + d] = acc;
    err [(size_t)row * DD + d] = x_in[(size_t)b * DD + d] - acc;
}

// ---------------------------------------------------------------------------
extern "C" void kernel_launch(void* const* d_in, const int* in_sizes, int n_in,
                              void* d_out, int out_size)
{
    const float* x_in  = (const float*)d_in[0];
    const float* x_ctx = (const float*)d_in[1];
    const float* Wff   = (const float*)d_in[2];
    const float* Wctx  = (const float*)d_in[3];
    const float* Wpred = (const float*)d_in[4];
    const float* bias  = (const float*)d_in[5];
    const float* avg   = (const float*)d_in[6];
    const int*   kptr  = (const int*)d_in[7];

    float* act  = (float*)d_out;                              // [B,C,N]
    float* pred = act  + (size_t)BB * CC * NN;                // [B,C,D]
    float* err  = pred + (size_t)BB * CC * DD;                // [B,C,D]

    dim3 g1(NN / 128, BB / 128, CC);
    drive_gemm<<<g1, 256>>>(x_in, x_ctx, Wff, Wctx, bias, act);

    topk_norm<<<BB * CC, NN>>>(avg, kptr, act);

    pred_err<<<BB * CC, DD>>>(x_in, Wpred, pred, err);
}

// round 3
// speedup vs baseline: 1.3521x; 1.3521x over previous
#include <cuda_runtime.h>
#include <math.h>

#define BB 1024
#define CC 64
#define DD 256
#define NN 512
#define K2 (2*DD)

// ---------------------------------------------------------------------------
// Kernel 1: drive[b,c,n] = x_in[b,:]·W_ff[c,:,n] + 0.3*x_ctx[b,:]·W_ctx[c,:,n] + bias
// One GEMM per c with K=512 (stacked halves). 128x128x16 tile, 8x8/thread,
// double-buffered smem (single __syncthreads per k-tile).
// ---------------------------------------------------------------------------
__global__ __launch_bounds__(256, 2) void drive_gemm(
    const float* __restrict__ x_in, const float* __restrict__ x_ctx,
    const float* __restrict__ Wff,  const float* __restrict__ Wctx,
    const float* __restrict__ bias, float* __restrict__ act)
{
    const int BM = 128, BN = 128, BK = 16;
    __shared__ float As[2][BK][BM];
    __shared__ float Bs[2][BK][BN];

    int c  = blockIdx.z;
    int m0 = blockIdx.y * BM;
    int n0 = blockIdx.x * BN;
    int tid = threadIdx.x;
    int tx = tid % 16, ty = tid / 16;

    float acc[8][8];
    #pragma unroll
    for (int i = 0; i < 8; i++)
        #pragma unroll
        for (int j = 0; j < 8; j++) acc[i][j] = 0.f;

    const float* WffC  = Wff  + (size_t)c * DD * NN;
    const float* WctxC = Wctx + (size_t)c * DD * NN;

    // ---- preload tile 0 into buffer 0 ----
    {
        #pragma unroll
        for (int i = 0; i < 2; i++) {
            int t = tid + i * 256;
            int m = t >> 2, kq = (t & 3) << 2;
            float4 v = *reinterpret_cast<const float4*>(x_in + (size_t)(m0 + m) * DD + kq);
            As[0][kq+0][m] = v.x;
            As[0][kq+1][m] = v.y;
            As[0][kq+2][m] = v.z;
            As[0][kq+3][m] = v.w;
        }
        #pragma unroll
        for (int i = 0; i < 2; i++) {
            int t = tid + i * 256;
            int kk = t >> 5, nq = (t & 31) << 2;
            *reinterpret_cast<float4*>(&Bs[0][kk][nq]) =
                *reinterpret_cast<const float4*>(WffC + (size_t)kk * NN + n0 + nq);
        }
    }
    __syncthreads();

    int cur = 0;
    for (int kt = 0; kt < K2 / BK; kt++) {
        float4 pa[2], pb[2];
        float  nscale = 1.0f;
        bool   has_next = (kt + 1 < K2 / BK);
        if (has_next) {
            int k0 = (kt + 1) * BK;
            const float* asrc = (k0 < DD) ? (x_in + k0) : (x_ctx + (k0 - DD));
            nscale = (k0 < DD) ? 1.0f : 0.3f;
            #pragma unroll
            for (int i = 0; i < 2; i++) {
                int t = tid + i * 256;
                int m = t >> 2, kq = (t & 3) << 2;
                pa[i] = *reinterpret_cast<const float4*>(asrc + (size_t)(m0 + m) * DD + kq);
            }
            const float* wsrc = (k0 < DD) ? (WffC + (size_t)k0 * NN)
                                          : (WctxC + (size_t)(k0 - DD) * NN);
            #pragma unroll
            for (int i = 0; i < 2; i++) {
                int t = tid + i * 256;
                int kk = t >> 5, nq = (t & 31) << 2;
                pb[i] = *reinterpret_cast<const float4*>(wsrc + (size_t)kk * NN + n0 + nq);
            }
        }

        #pragma unroll
        for (int kk = 0; kk < BK; kk++) {
            float ra[8], rb[8];
            *reinterpret_cast<float4*>(&ra[0]) = *reinterpret_cast<const float4*>(&As[cur][kk][ty * 8]);
            *reinterpret_cast<float4*>(&ra[4]) = *reinterpret_cast<const float4*>(&As[cur][kk][ty * 8 + 4]);
            *reinterpret_cast<float4*>(&rb[0]) = *reinterpret_cast<const float4*>(&Bs[cur][kk][tx * 8]);
            *reinterpret_cast<float4*>(&rb[4]) = *reinterpret_cast<const float4*>(&Bs[cur][kk][tx * 8 + 4]);
            #pragma unroll
            for (int i = 0; i < 8; i++)
                #pragma unroll
                for (int j = 0; j < 8; j++)
                    acc[i][j] = fmaf(ra[i], rb[j], acc[i][j]);
        }

        if (has_next) {
            int nxt = cur ^ 1;
            #pragma unroll
            for (int i = 0; i < 2; i++) {
                int t = tid + i * 256;
                int m = t >> 2, kq = (t & 3) << 2;
                As[nxt][kq+0][m] = pa[i].x * nscale;
                As[nxt][kq+1][m] = pa[i].y * nscale;
                As[nxt][kq+2][m] = pa[i].z * nscale;
                As[nxt][kq+3][m] = pa[i].w * nscale;
            }
            #pragma unroll
            for (int i = 0; i < 2; i++) {
                int t = tid + i * 256;
                int kk = t >> 5, nq = (t & 31) << 2;
                *reinterpret_cast<float4*>(&Bs[nxt][kk][nq]) = pb[i];
            }
            __syncthreads();
            cur = nxt;
        }
    }

    const float* bb = bias + (size_t)c * NN + n0 + tx * 8;
    #pragma unroll
    for (int i = 0; i < 8; i++) {
        int m = m0 + ty * 8 + i;
        float* dst = act + ((size_t)m * CC + c) * NN + n0 + tx * 8;
        #pragma unroll
        for (int j = 0; j < 8; j += 4) {
            float4 o;
            o.x = acc[i][j + 0] + bb[j + 0];
            o.y = acc[i][j + 1] + bb[j + 1];
            o.z = acc[i][j + 2] + bb[j + 2];
            o.w = acc[i][j + 3] + bb[j + 3];
            *reinterpret_cast<float4*>(dst + j) = o;
        }
    }
}

// ---------------------------------------------------------------------------
// Kernel 2 (fused): per-row (b,c) radix-select k-WTA + normalize + sparse
// prediction + error. One block of 512 threads per row.
// ---------------------------------------------------------------------------
__device__ __forceinline__ unsigned f2ord(float f) {
    unsigned u = __float_as_uint(f);
    return (u & 0x80000000u) ? ~u : (u | 0x80000000u);
}

__global__ __launch_bounds__(NN) void topk_pred(
    const float* __restrict__ avg, const int* __restrict__ kptr,
    const float* __restrict__ x_in, const float* __restrict__ Wp,
    float* __restrict__ act, float* __restrict__ pred, float* __restrict__ err)
{
    int row = blockIdx.x;       // b*C + c
    int c   = row % CC;
    int b   = row / CC;
    int n   = threadIdx.x;      // 512

    __shared__ unsigned hist[256];
    __shared__ unsigned s_sel, s_rnew;
    __shared__ unsigned s_thr;
    __shared__ float    warpsum[16];
    __shared__ float    ssum;
    __shared__ float    vv[64];
    __shared__ int      ii[64];
    __shared__ int      scnt;
    __shared__ float    part[NN];

    float drive   = act[(size_t)row * NN + n];
    float boost   = log1pf(0.05f / (avg[(size_t)c * NN + n] + 1e-6f));
    float boosted = drive + boost;        // HOMEOSTASIS*100 == 1.0
    unsigned u    = f2ord(boosted);

    if (n == 0) scnt = 0;

    // ---- 4-pass radix select of k-th largest ----
    int k = *kptr;
    bool active = true;
    int  r = k;
    #pragma unroll
    for (int pass = 0; pass < 4; pass++) {
        int shift = 24 - pass * 8;
        if (n < 256) hist[n] = 0;
        __syncthreads();
        unsigned mybin = (u >> shift) & 0xFFu;
        if (active) atomicAdd(&hist[mybin], 1u);
        __syncthreads();
        if (n < 32) {
            unsigned h[8]; unsigned lsum = 0;
            #pragma unroll
            for (int j = 0; j < 8; j++) { h[j] = hist[n * 8 + j]; lsum += h[j]; }
            unsigned inc = lsum;
            #pragma unroll
            for (int off = 1; off < 32; off <<= 1) {
                unsigned v = __shfl_up_sync(0xffffffffu, inc, off);
                if (n >= off) inc += v;
            }
            unsigned total   = __shfl_sync(0xffffffffu, inc, 31);
            unsigned running = total - inc;   // elems in bins above this lane's range
            #pragma unroll
            for (int j = 7; j >= 0; j--) {
                if (running < (unsigned)r && (unsigned)r <= running + h[j]) {
                    s_sel  = (unsigned)(n * 8 + j);
                    s_rnew = (unsigned)r - running;
                }
                running += h[j];
            }
        }
        __syncthreads();
        unsigned sel = s_sel;
        r = (int)s_rnew;
        active = active && (((u >> shift) & 0xFFu) == sel);
    }
    // all surviving 'active' threads hold u exactly equal to the k-th largest
    if (active) s_thr = u;
    __syncthreads();
    unsigned thr_u = s_thr;

    bool  win = (u >= thr_u);
    float a   = win ? fmaxf(drive, 0.f) : 0.f;

    // ---- block reduction of sum(a) ----
    float s = a;
    #pragma unroll
    for (int off = 16; off > 0; off >>= 1) s += __shfl_down_sync(0xffffffffu, s, off);
    if ((n & 31) == 0) warpsum[n >> 5] = s;
    __syncthreads();
    if (n < 16) {
        float t = warpsum[n];
        #pragma unroll
        for (int off = 8; off > 0; off >>= 1) t += __shfl_down_sync(0xffffu, t, off);
        if (n == 0) ssum = t;
    }
    __syncthreads();

    float scale = (float)k / (ssum + 1e-8f);
    float outv  = a * scale;
    act[(size_t)row * NN + n] = outv;

    if (win) {
        int p = atomicAdd(&scnt, 1);
        if (p < 64) { ii[p] = n; vv[p] = outv; }
    }
    __syncthreads();

    // ---- sparse prediction: pred[d] = sum_j vv[j] * Wp[c, ii[j], d] ----
    int cnt  = scnt < 64 ? scnt : 64;
    int d    = n & 255;
    int half = n >> 8;
    const float* WpC = Wp + (size_t)c * NN * DD;
    float acc = 0.f;
    for (int j = half; j < cnt; j += 2)
        acc = fmaf(vv[j], WpC[(size_t)ii[j] * DD + d], acc);
    part[n] = acc;
    __syncthreads();
    if (n < 256) {
        float p2 = part[n] + part[n + 256];
        pred[(size_t)row * DD + d] = p2;
        err [(size_t)row * DD + d] = x_in[(size_t)b * DD + d] - p2;
    }
}

// ---------------------------------------------------------------------------
extern "C" void kernel_launch(void* const* d_in, const int* in_sizes, int n_in,
                              void* d_out, int out_size)
{
    const float* x_in  = (const float*)d_in[0];
    const float* x_ctx = (const float*)d_in[1];
    const float* Wff   = (const float*)d_in[2];
    const float* Wctx  = (const float*)d_in[3];
    const float* Wpred = (const float*)d_in[4];
    const float* bias  = (const float*)d_in[5];
    const float* avg   = (const float*)d_in[6];
    const int*   kptr  = (const int*)d_in[7];

    float* act  = (float*)d_out;                              // [B,C,N]
    float* pred = act  + (size_t)BB * CC * NN;                // [B,C,D]
    float* err  = pred + (size_t)BB * CC * DD;                // [B,C,D]

    dim3 g1(NN / 128, BB / 128, CC);
    drive_gemm<<<g1, 256>>>(x_in, x_ctx, Wff, Wctx, bias, act);

    topk_pred<<<BB * CC, NN>>>(avg, kptr, x_in, Wpred, act, pred, err);
}

// round 4
// speedup vs baseline: 1.4885x; 1.1009x over previous
#include <cuda_runtime.h>
#include <math.h>

#define BB 1024
#define CC 64
#define DD 256
#define NN 512
#define K2 (2*DD)

// ---- packed fp32 helpers (Blackwell f32x2 pipe) ----
__device__ __forceinline__ unsigned long long pack2(float lo, float hi) {
    unsigned long long r;
    asm("mov.b64 %0, {%1, %2};" : "=l"(r) : "f"(lo), "f"(hi));
    return r;
}
__device__ __forceinline__ void fma2(unsigned long long& d,
                                     unsigned long long a, unsigned long long b) {
    asm("fma.rn.f32x2 %0, %1, %2, %0;" : "+l"(d) : "l"(a), "l"(b));
}
__device__ __forceinline__ void unpack2(unsigned long long v, float& lo, float& hi) {
    asm("mov.b64 {%0, %1}, %2;" : "=f"(lo), "=f"(hi) : "l"(v));
}

// ---------------------------------------------------------------------------
// Kernel 1: drive[b,c,n] = x_in·W_ff + 0.3*x_ctx·W_ctx + bias  (K=512 stacked)
// 128x128x16 tile, 8x8/thread via 8x4 packed f32x2 accumulators, double-buffered.
// ---------------------------------------------------------------------------
__global__ __launch_bounds__(256, 2) void drive_gemm(
    const float* __restrict__ x_in, const float* __restrict__ x_ctx,
    const float* __restrict__ Wff,  const float* __restrict__ Wctx,
    const float* __restrict__ bias, float* __restrict__ act)
{
    const int BM = 128, BN = 128, BK = 16;
    __shared__ float As[2][BK][BM];
    __shared__ float Bs[2][BK][BN];

    int c  = blockIdx.z;
    int m0 = blockIdx.y * BM;
    int n0 = blockIdx.x * BN;
    int tid = threadIdx.x;
    int tx = tid % 16, ty = tid / 16;

    unsigned long long acc2[8][4];
    #pragma unroll
    for (int i = 0; i < 8; i++)
        #pragma unroll
        for (int j = 0; j < 4; j++) acc2[i][j] = 0ull;

    const float* WffC  = Wff  + (size_t)c * DD * NN;
    const float* WctxC = Wctx + (size_t)c * DD * NN;

    // preload tile 0
    {
        #pragma unroll
        for (int i = 0; i < 2; i++) {
            int t = tid + i * 256;
            int m = t >> 2, kq = (t & 3) << 2;
            float4 v = *reinterpret_cast<const float4*>(x_in + (size_t)(m0 + m) * DD + kq);
            As[0][kq+0][m] = v.x; As[0][kq+1][m] = v.y;
            As[0][kq+2][m] = v.z; As[0][kq+3][m] = v.w;
        }
        #pragma unroll
        for (int i = 0; i < 2; i++) {
            int t = tid + i * 256;
            int kk = t >> 5, nq = (t & 31) << 2;
            *reinterpret_cast<float4*>(&Bs[0][kk][nq]) =
                *reinterpret_cast<const float4*>(WffC + (size_t)kk * NN + n0 + nq);
        }
    }
    __syncthreads();

    int cur = 0;
    for (int kt = 0; kt < K2 / BK; kt++) {
        float4 pa[2], pb[2];
        float  nscale = 1.0f;
        bool   has_next = (kt + 1 < K2 / BK);
        if (has_next) {
            int k0 = (kt + 1) * BK;
            const float* asrc = (k0 < DD) ? (x_in + k0) : (x_ctx + (k0 - DD));
            nscale = (k0 < DD) ? 1.0f : 0.3f;
            #pragma unroll
            for (int i = 0; i < 2; i++) {
                int t = tid + i * 256;
                int m = t >> 2, kq = (t & 3) << 2;
                pa[i] = *reinterpret_cast<const float4*>(asrc + (size_t)(m0 + m) * DD + kq);
            }
            const float* wsrc = (k0 < DD) ? (WffC + (size_t)k0 * NN)
                                          : (WctxC + (size_t)(k0 - DD) * NN);
            #pragma unroll
            for (int i = 0; i < 2; i++) {
                int t = tid + i * 256;
                int kk = t >> 5, nq = (t & 31) << 2;
                pb[i] = *reinterpret_cast<const float4*>(wsrc + (size_t)kk * NN + n0 + nq);
            }
        }

        #pragma unroll
        for (int kk = 0; kk < BK; kk++) {
            // B: 8 consecutive floats as 4 packed pairs (16B-aligned)
            const double2* bp = reinterpret_cast<const double2*>(&Bs[cur][kk][tx * 8]);
            double2 b01 = bp[0], b23 = bp[1];
            unsigned long long b2[4];
            b2[0] = __double_as_longlong(b01.x);
            b2[1] = __double_as_longlong(b01.y);
            b2[2] = __double_as_longlong(b23.x);
            b2[3] = __double_as_longlong(b23.y);
            // A: 8 floats, each duplicated into both lanes
            float ra[8];
            *reinterpret_cast<float4*>(&ra[0]) = *reinterpret_cast<const float4*>(&As[cur][kk][ty * 8]);
            *reinterpret_cast<float4*>(&ra[4]) = *reinterpret_cast<const float4*>(&As[cur][kk][ty * 8 + 4]);
            unsigned long long a2[8];
            #pragma unroll
            for (int i = 0; i < 8; i++) a2[i] = pack2(ra[i], ra[i]);

            #pragma unroll
            for (int i = 0; i < 8; i++)
                #pragma unroll
                for (int j = 0; j < 4; j++)
                    fma2(acc2[i][j], a2[i], b2[j]);
        }

        if (has_next) {
            int nxt = cur ^ 1;
            #pragma unroll
            for (int i = 0; i < 2; i++) {
                int t = tid + i * 256;
                int m = t >> 2, kq = (t & 3) << 2;
                As[nxt][kq+0][m] = pa[i].x * nscale;
                As[nxt][kq+1][m] = pa[i].y * nscale;
                As[nxt][kq+2][m] = pa[i].z * nscale;
                As[nxt][kq+3][m] = pa[i].w * nscale;
            }
            #pragma unroll
            for (int i = 0; i < 2; i++) {
                int t = tid + i * 256;
                int kk = t >> 5, nq = (t & 31) << 2;
                *reinterpret_cast<float4*>(&Bs[nxt][kk][nq]) = pb[i];
            }
            __syncthreads();
            cur = nxt;
        }
    }

    const float* bb = bias + (size_t)c * NN + n0 + tx * 8;
    #pragma unroll
    for (int i = 0; i < 8; i++) {
        int m = m0 + ty * 8 + i;
        float* dst = act + ((size_t)m * CC + c) * NN + n0 + tx * 8;
        #pragma unroll
        for (int j = 0; j < 2; j++) {
            float4 o;
            unpack2(acc2[i][j*2+0], o.x, o.y);
            unpack2(acc2[i][j*2+1], o.z, o.w);
            o.x += bb[j*4+0]; o.y += bb[j*4+1];
            o.z += bb[j*4+2]; o.w += bb[j*4+3];
            *reinterpret_cast<float4*>(dst + j*4) = o;
        }
    }
}

// ---------------------------------------------------------------------------
// Kernel 2 (fused): radix-select k-WTA (early exit) + normalize + sparse
// prediction + error. One 512-thread block per (b,c) row.
// ---------------------------------------------------------------------------
__device__ __forceinline__ unsigned f2ord(float f) {
    unsigned u = __float_as_uint(f);
    return (u & 0x80000000u) ? ~u : (u | 0x80000000u);
}

__global__ __launch_bounds__(NN) void topk_pred(
    const float* __restrict__ avg, const int* __restrict__ kptr,
    const float* __restrict__ x_in, const float* __restrict__ Wp,
    float* __restrict__ act, float* __restrict__ pred, float* __restrict__ err)
{
    int row = blockIdx.x;       // b*C + c
    int c   = row % CC;
    int b   = row / CC;
    int n   = threadIdx.x;      // 512

    __shared__ unsigned hist[256];
    __shared__ unsigned s_sel, s_rnew, s_cnt;
    __shared__ unsigned s_thr;
    __shared__ float    warpsum[16];
    __shared__ float    ssum;
    __shared__ float    vv[64];
    __shared__ int      ii[64];
    __shared__ int      scnt;
    __shared__ float    part[NN];

    float drive   = act[(size_t)row * NN + n];
    float boost   = log1pf(0.05f / (avg[(size_t)c * NN + n] + 1e-6f));
    float boosted = drive + boost;        // HOMEOSTASIS*100 == 1.0
    unsigned u    = f2ord(boosted);

    if (n == 0) scnt = 0;

    // ---- radix select of k-th largest, early exit when bin is unique ----
    int k = *kptr;
    bool active = true;
    int  r = k;
    #pragma unroll
    for (int pass = 0; pass < 4; pass++) {
        int shift = 24 - pass * 8;
        if (n < 256) hist[n] = 0;
        __syncthreads();
        unsigned mybin = (u >> shift) & 0xFFu;
        if (active) atomicAdd(&hist[mybin], 1u);
        __syncthreads();
        if (n < 32) {
            unsigned h[8]; unsigned lsum = 0;
            #pragma unroll
            for (int j = 0; j < 8; j++) { h[j] = hist[n * 8 + j]; lsum += h[j]; }
            unsigned inc = lsum;
            #pragma unroll
            for (int off = 1; off < 32; off <<= 1) {
                unsigned v = __shfl_up_sync(0xffffffffu, inc, off);
                if (n >= off) inc += v;
            }
            unsigned total   = __shfl_sync(0xffffffffu, inc, 31);
            unsigned running = total - inc;   // elems in bins above this lane's range
            #pragma unroll
            for (int j = 7; j >= 0; j--) {
                if (running < (unsigned)r && (unsigned)r <= running + h[j]) {
                    s_sel  = (unsigned)(n * 8 + j);
                    s_rnew = (unsigned)r - running;
                    s_cnt  = h[j];
                }
                running += h[j];
            }
        }
        __syncthreads();
        unsigned sel  = s_sel;
        unsigned csel = s_cnt;
        r = (int)s_rnew;
        active = active && (mybin == sel);
        if (csel == 1u || pass == 3) {
            if (active) s_thr = u;   // unique (or tie-identical) k-th value
            break;                   // uniform: csel/pass identical across block
        }
    }
    __syncthreads();
    unsigned thr_u = s_thr;

    bool  win = (u >= thr_u);
    float a   = win ? fmaxf(drive, 0.f) : 0.f;

    // ---- block reduction of sum(a) ----
    float s = a;
    #pragma unroll
    for (int off = 16; off > 0; off >>= 1) s += __shfl_down_sync(0xffffffffu, s, off);
    if ((n & 31) == 0) warpsum[n >> 5] = s;
    __syncthreads();
    if (n < 16) {
        float t = warpsum[n];
        #pragma unroll
        for (int off = 8; off > 0; off >>= 1) t += __shfl_down_sync(0xffffu, t, off);
        if (n == 0) ssum = t;
    }
    __syncthreads();

    float scale = (float)k / (ssum + 1e-8f);
    float outv  = a * scale;
    act[(size_t)row * NN + n] = outv;

    if (win) {
        int p = atomicAdd(&scnt, 1);
        if (p < 64) { ii[p] = n; vv[p] = outv; }
    }
    __syncthreads();

    // ---- sparse prediction: pred[d] = sum_j vv[j] * Wp[c, ii[j], d] ----
    int cnt  = scnt < 64 ? scnt : 64;
    int d    = n & 255;
    int half = n >> 8;
    const float* WpC = Wp + (size_t)c * NN * DD;
    float acc = 0.f;
    for (int j = half; j < cnt; j += 2)
        acc = fmaf(vv[j], __ldg(WpC + (size_t)ii[j] * DD + d), acc);
    part[n] = acc;
    __syncthreads();
    if (n < 256) {
        float p2 = part[n] + part[n + 256];
        pred[(size_t)row * DD + d] = p2;
        err [(size_t)row * DD + d] = x_in[(size_t)b * DD + d] - p2;
    }
}

// ---------------------------------------------------------------------------
extern "C" void kernel_launch(void* const* d_in, const int* in_sizes, int n_in,
                              void* d_out, int out_size)
{
    const float* x_in  = (const float*)d_in[0];
    const float* x_ctx = (const float*)d_in[1];
    const float* Wff   = (const float*)d_in[2];
    const float* Wctx  = (const float*)d_in[3];
    const float* Wpred = (const float*)d_in[4];
    const float* bias  = (const float*)d_in[5];
    const float* avg   = (const float*)d_in[6];
    const int*   kptr  = (const int*)d_in[7];

    float* act  = (float*)d_out;                              // [B,C,N]
    float* pred = act  + (size_t)BB * CC * NN;                // [B,C,D]
    float* err  = pred + (size_t)BB * CC * DD;                // [B,C,D]

    dim3 g1(NN / 128, BB / 128, CC);
    drive_gemm<<<g1, 256>>>(x_in, x_ctx, Wff, Wctx, bias, act);

    topk_pred<<<BB * CC, NN>>>(avg, kptr, x_in, Wpred, act, pred, err);
}

// round 5
// speedup vs baseline: 1.8990x; 1.2758x over previous
#include <cuda_runtime.h>
#include <math.h>

#define BB 1024
#define CC 64
#define DD 256
#define NN 512
#define K2 (2*DD)

__device__ float g_boost[CC*NN];

// ---------------------------------------------------------------------------
// Kernel 0: boost[c,n] = log1p(0.05/(avg+1e-6))   (batch-independent!)
// ---------------------------------------------------------------------------
__global__ void boost_kernel(const float* __restrict__ avg) {
    int i = blockIdx.x * blockDim.x + threadIdx.x;
    if (i < CC * NN) g_boost[i] = log1pf(0.05f / (avg[i] + 1e-6f));
}

// ---- packed fp32 helpers (Blackwell f32x2 pipe) ----
__device__ __forceinline__ unsigned long long pack2(float lo, float hi) {
    unsigned long long r;
    asm("mov.b64 %0, {%1, %2};" : "=l"(r) : "f"(lo), "f"(hi));
    return r;
}
__device__ __forceinline__ void fma2(unsigned long long& d,
                                     unsigned long long a, unsigned long long b) {
    asm("fma.rn.f32x2 %0, %1, %2, %0;" : "+l"(d) : "l"(a), "l"(b));
}
__device__ __forceinline__ void unpack2(unsigned long long v, float& lo, float& hi) {
    asm("mov.b64 {%0, %1}, %2;" : "=f"(lo), "=f"(hi) : "l"(v));
}

// ---------------------------------------------------------------------------
// Kernel 1: drive GEMM (unchanged from round 4 — 747us, 64% of SIMT ceiling)
// ---------------------------------------------------------------------------
__global__ __launch_bounds__(256, 2) void drive_gemm(
    const float* __restrict__ x_in, const float* __restrict__ x_ctx,
    const float* __restrict__ Wff,  const float* __restrict__ Wctx,
    const float* __restrict__ bias, float* __restrict__ act)
{
    const int BM = 128, BN = 128, BK = 16;
    __shared__ float As[2][BK][BM];
    __shared__ float Bs[2][BK][BN];

    int c  = blockIdx.z;
    int m0 = blockIdx.y * BM;
    int n0 = blockIdx.x * BN;
    int tid = threadIdx.x;
    int tx = tid % 16, ty = tid / 16;

    unsigned long long acc2[8][4];
    #pragma unroll
    for (int i = 0; i < 8; i++)
        #pragma unroll
        for (int j = 0; j < 4; j++) acc2[i][j] = 0ull;

    const float* WffC  = Wff  + (size_t)c * DD * NN;
    const float* WctxC = Wctx + (size_t)c * DD * NN;

    {
        #pragma unroll
        for (int i = 0; i < 2; i++) {
            int t = tid + i * 256;
            int m = t >> 2, kq = (t & 3) << 2;
            float4 v = *reinterpret_cast<const float4*>(x_in + (size_t)(m0 + m) * DD + kq);
            As[0][kq+0][m] = v.x; As[0][kq+1][m] = v.y;
            As[0][kq+2][m] = v.z; As[0][kq+3][m] = v.w;
        }
        #pragma unroll
        for (int i = 0; i < 2; i++) {
            int t = tid + i * 256;
            int kk = t >> 5, nq = (t & 31) << 2;
            *reinterpret_cast<float4*>(&Bs[0][kk][nq]) =
                *reinterpret_cast<const float4*>(WffC + (size_t)kk * NN + n0 + nq);
        }
    }
    __syncthreads();

    int cur = 0;
    for (int kt = 0; kt < K2 / BK; kt++) {
        float4 pa[2], pb[2];
        float  nscale = 1.0f;
        bool   has_next = (kt + 1 < K2 / BK);
        if (has_next) {
            int k0 = (kt + 1) * BK;
            const float* asrc = (k0 < DD) ? (x_in + k0) : (x_ctx + (k0 - DD));
            nscale = (k0 < DD) ? 1.0f : 0.3f;
            #pragma unroll
            for (int i = 0; i < 2; i++) {
                int t = tid + i * 256;
                int m = t >> 2, kq = (t & 3) << 2;
                pa[i] = *reinterpret_cast<const float4*>(asrc + (size_t)(m0 + m) * DD + kq);
            }
            const float* wsrc = (k0 < DD) ? (WffC + (size_t)k0 * NN)
                                          : (WctxC + (size_t)(k0 - DD) * NN);
            #pragma unroll
            for (int i = 0; i < 2; i++) {
                int t = tid + i * 256;
                int kk = t >> 5, nq = (t & 31) << 2;
                pb[i] = *reinterpret_cast<const float4*>(wsrc + (size_t)kk * NN + n0 + nq);
            }
        }

        #pragma unroll
        for (int kk = 0; kk < BK; kk++) {
            const double2* bp = reinterpret_cast<const double2*>(&Bs[cur][kk][tx * 8]);
            double2 b01 = bp[0], b23 = bp[1];
            unsigned long long b2[4];
            b2[0] = __double_as_longlong(b01.x);
            b2[1] = __double_as_longlong(b01.y);
            b2[2] = __double_as_longlong(b23.x);
            b2[3] = __double_as_longlong(b23.y);
            float ra[8];
            *reinterpret_cast<float4*>(&ra[0]) = *reinterpret_cast<const float4*>(&As[cur][kk][ty * 8]);
            *reinterpret_cast<float4*>(&ra[4]) = *reinterpret_cast<const float4*>(&As[cur][kk][ty * 8 + 4]);
            unsigned long long a2[8];
            #pragma unroll
            for (int i = 0; i < 8; i++) a2[i] = pack2(ra[i], ra[i]);

            #pragma unroll
            for (int i = 0; i < 8; i++)
                #pragma unroll
                for (int j = 0; j < 4; j++)
                    fma2(acc2[i][j], a2[i], b2[j]);
        }

        if (has_next) {
            int nxt = cur ^ 1;
            #pragma unroll
            for (int i = 0; i < 2; i++) {
                int t = tid + i * 256;
                int m = t >> 2, kq = (t & 3) << 2;
                As[nxt][kq+0][m] = pa[i].x * nscale;
                As[nxt][kq+1][m] = pa[i].y * nscale;
                As[nxt][kq+2][m] = pa[i].z * nscale;
                As[nxt][kq+3][m] = pa[i].w * nscale;
            }
            #pragma unroll
            for (int i = 0; i < 2; i++) {
                int t = tid + i * 256;
                int kk = t >> 5, nq = (t & 31) << 2;
                *reinterpret_cast<float4*>(&Bs[nxt][kk][nq]) = pb[i];
            }
            __syncthreads();
            cur = nxt;
        }
    }

    const float* bb = bias + (size_t)c * NN + n0 + tx * 8;
    #pragma unroll
    for (int i = 0; i < 8; i++) {
        int m = m0 + ty * 8 + i;
        float* dst = act + ((size_t)m * CC + c) * NN + n0 + tx * 8;
        #pragma unroll
        for (int j = 0; j < 2; j++) {
            float4 o;
            unpack2(acc2[i][j*2+0], o.x, o.y);
            unpack2(acc2[i][j*2+1], o.z, o.w);
            o.x += bb[j*4+0]; o.y += bb[j*4+1];
            o.z += bb[j*4+2]; o.w += bb[j*4+3];
            *reinterpret_cast<float4*>(dst + j*4) = o;
        }
    }
}

// ---------------------------------------------------------------------------
// Kernel 2: warp-per-row k-WTA (binary search on ordered uints) + normalize
//           + sparse pred/err. 8 rows per 256-thread block. No barriers/atomics.
// ---------------------------------------------------------------------------
__device__ __forceinline__ unsigned f2ord(float f) {
    unsigned u = __float_as_uint(f);
    return (u & 0x80000000u) ? ~u : (u | 0x80000000u);
}

__global__ __launch_bounds__(256) void topk_pred(
    const int* __restrict__ kptr, const float* __restrict__ x_in,
    const float* __restrict__ Wp,
    float* __restrict__ act, float* __restrict__ pred, float* __restrict__ err)
{
    int lane = threadIdx.x & 31;
    int w    = threadIdx.x >> 5;
    int row  = blockIdx.x * 8 + w;          // b*C + c
    int c = row & (CC - 1);
    int b = row >> 6;

    __shared__ float s_vv[8][64];
    __shared__ int   s_ii[8][64];

    const float4* arow = reinterpret_cast<const float4*>(act + (size_t)row * NN);
    const float4* brow = reinterpret_cast<const float4*>(g_boost + (size_t)c * NN);

    float    f[16];
    unsigned u[16];
    #pragma unroll
    for (int i = 0; i < 4; i++) {
        float4 a  = arow[i * 32 + lane];
        float4 bo = brow[i * 32 + lane];
        f[i*4+0] = a.x; f[i*4+1] = a.y; f[i*4+2] = a.z; f[i*4+3] = a.w;
        u[i*4+0] = f2ord(a.x + bo.x);
        u[i*4+1] = f2ord(a.y + bo.y);
        u[i*4+2] = f2ord(a.z + bo.z);
        u[i*4+3] = f2ord(a.w + bo.w);
    }

    int k = *kptr;

    // range narrowing: T in [min-of-lane-maxes, warp-max]  (valid when k<=32)
    unsigned lmax = 0;
    #pragma unroll
    for (int s = 0; s < 16; s++) lmax = max(lmax, u[s]);
    unsigned mx = lmax, lb = lmax;
    #pragma unroll
    for (int o = 16; o; o >>= 1) {
        mx = max(mx, __shfl_xor_sync(0xffffffffu, mx, o));
        lb = min(lb, __shfl_xor_sync(0xffffffffu, lb, o));
    }
    if (k > 32) lb = 0u;

    // binary search for T = largest v with count(u >= v) >= k  (== k-th largest)
    unsigned diff = mx ^ lb;
    unsigned T;
    int topbit;
    if (diff == 0u) { T = mx; topbit = -1; }
    else {
        topbit = 31 - __clz(diff);
        unsigned mask = (topbit == 31) ? 0xFFFFFFFFu : ((2u << topbit) - 1u);
        T = mx & ~mask;
    }
    for (int bit = topbit; bit >= 0; --bit) {
        unsigned cand = T | (1u << bit);
        int cnt = 0;
        #pragma unroll
        for (int s = 0; s < 16; s++) cnt += (u[s] >= cand) ? 1 : 0;
        #pragma unroll
        for (int o = 16; o; o >>= 1) cnt += __shfl_xor_sync(0xffffffffu, cnt, o);
        if (cnt >= k) T = cand;
    }

    // sum of relu(drive) over winners -> normalization scale
    float lsum = 0.f;
    #pragma unroll
    for (int s = 0; s < 16; s++) {
        float r = fmaxf(f[s], 0.f);
        lsum += (u[s] >= T) ? r : 0.f;
    }
    #pragma unroll
    for (int o = 16; o; o >>= 1) lsum += __shfl_xor_sync(0xffffffffu, lsum, o);
    float scale = (float)k / (lsum + 1e-8f);

    // write normalized activation + ballot-compact nonzero winners
    float4* orow = reinterpret_cast<float4*>(act + (size_t)row * NN);
    int cnt_total = 0;
    #pragma unroll
    for (int i = 0; i < 4; i++) {
        float ov[4];
        #pragma unroll
        for (int q = 0; q < 4; q++) {
            int s = i * 4 + q;
            float r   = fmaxf(f[s], 0.f);
            bool win  = (u[s] >= T);
            float val = win ? r * scale : 0.f;
            ov[q] = val;
            bool put = win && (r > 0.f);
            unsigned m = __ballot_sync(0xffffffffu, put);
            if (put) {
                int pos = cnt_total + __popc(m & ((1u << lane) - 1u));
                if (pos < 64) {
                    s_ii[w][pos] = i * 128 + lane * 4 + q;
                    s_vv[w][pos] = val;
                }
            }
            cnt_total += __popc(m);
        }
        orow[i * 32 + lane] = make_float4(ov[0], ov[1], ov[2], ov[3]);
    }
    if (cnt_total > 64) cnt_total = 64;
    __syncwarp();

    // sparse prediction: pred[d] = sum_j vv[j] * Wp[c, ii[j], d]
    const float*  WpC = Wp + (size_t)c * NN * DD;
    float4 acc0 = make_float4(0.f, 0.f, 0.f, 0.f);
    float4 acc1 = make_float4(0.f, 0.f, 0.f, 0.f);
    for (int j = 0; j < cnt_total; j++) {
        float vj = s_vv[w][j];
        const float4* wr = reinterpret_cast<const float4*>(WpC + (size_t)s_ii[w][j] * DD);
        float4 w0 = wr[lane];
        float4 w1 = wr[lane + 32];
        acc0.x = fmaf(vj, w0.x, acc0.x); acc0.y = fmaf(vj, w0.y, acc0.y);
        acc0.z = fmaf(vj, w0.z, acc0.z); acc0.w = fmaf(vj, w0.w, acc0.w);
        acc1.x = fmaf(vj, w1.x, acc1.x); acc1.y = fmaf(vj, w1.y, acc1.y);
        acc1.z = fmaf(vj, w1.z, acc1.z); acc1.w = fmaf(vj, w1.w, acc1.w);
    }

    const float4* xr = reinterpret_cast<const float4*>(x_in + (size_t)b * DD);
    float4 x0 = xr[lane], x1 = xr[lane + 32];
    float4* prow = reinterpret_cast<float4*>(pred + (size_t)row * DD);
    float4* erow = reinterpret_cast<float4*>(err  + (size_t)row * DD);
    prow[lane]      = acc0;
    prow[lane + 32] = acc1;
    erow[lane]      = make_float4(x0.x - acc0.x, x0.y - acc0.y, x0.z - acc0.z, x0.w - acc0.w);
    erow[lane + 32] = make_float4(x1.x - acc1.x, x1.y - acc1.y, x1.z - acc1.z, x1.w - acc1.w);
}

// ---------------------------------------------------------------------------
extern "C" void kernel_launch(void* const* d_in, const int* in_sizes, int n_in,
                              void* d_out, int out_size)
{
    const float* x_in  = (const float*)d_in[0];
    const float* x_ctx = (const float*)d_in[1];
    const float* Wff   = (const float*)d_in[2];
    const float* Wctx  = (const float*)d_in[3];
    const float* Wpred = (const float*)d_in[4];
    const float* bias  = (const float*)d_in[5];
    const float* avg   = (const float*)d_in[6];
    const int*   kptr  = (const int*)d_in[7];

    float* act  = (float*)d_out;                              // [B,C,N]
    float* pred = act  + (size_t)BB * CC * NN;                // [B,C,D]
    float* err  = pred + (size_t)BB * CC * DD;                // [B,C,D]

    boost_kernel<<<(CC * NN + 255) / 256, 256>>>(avg);

    dim3 g1(NN / 128, BB / 128, CC);
    drive_gemm<<<g1, 256>>>(x_in, x_ctx, Wff, Wctx, bias, act);

    topk_pred<<<BB * CC / 8, 256>>>(kptr, x_in, Wpred, act, pred, err);
}

// round 7
// speedup vs baseline: 2.1720x; 1.1438x over previous
#include <cuda_runtime.h>
#include <math.h>

#define BB 1024
#define CC 64
#define DD 256
#define NN 512
#define K2 (2*DD)
#define DELTA 1e-4f

__device__ float g_boost[CC*NN];

// ---------------------------------------------------------------------------
// Kernel 0: boost[c,n] = log1p(0.05/(avg+1e-6))   (batch-independent)
// ---------------------------------------------------------------------------
__global__ void boost_kernel(const float* __restrict__ avg) {
    int i = blockIdx.x * blockDim.x + threadIdx.x;
    if (i < CC * NN) g_boost[i] = log1pf(0.05f / (avg[i] + 1e-6f));
}

// ---- tf32 helpers ----
__device__ __forceinline__ unsigned tf32_hi(float x) {
    unsigned r;
    asm("cvt.rna.tf32.f32 %0, %1;" : "=r"(r) : "f"(x));
    return r;
}
__device__ __forceinline__ void mma_tf32(
    float& c0, float& c1, float& c2, float& c3,
    unsigned a0, unsigned a1, unsigned a2, unsigned a3,
    unsigned b0, unsigned b1)
{
    asm("mma.sync.aligned.m16n8k8.row.col.f32.tf32.tf32.f32 "
        "{%0,%1,%2,%3},{%4,%5,%6,%7},{%8,%9},{%0,%1,%2,%3};"
        : "+f"(c0), "+f"(c1), "+f"(c2), "+f"(c3)
        : "r"(a0), "r"(a1), "r"(a2), "r"(a3), "r"(b0), "r"(b1));
}

// ---------------------------------------------------------------------------
// Kernel 1: drive GEMM via 3xTF32 (round-6 kernel; numerically ~1e-6 correct)
// ---------------------------------------------------------------------------
__global__ __launch_bounds__(256) void drive_gemm(
    const float* __restrict__ x_in, const float* __restrict__ x_ctx,
    const float* __restrict__ Wff,  const float* __restrict__ Wctx,
    const float* __restrict__ bias, float* __restrict__ act)
{
    const int BM = 128, BN = 128, BK = 16, LD = 136;
    __shared__ float As[2][BK][LD];
    __shared__ float Bs[2][BK][LD];

    int c  = blockIdx.z;
    int m0 = blockIdx.y * BM;
    int n0 = blockIdx.x * BN;
    int tid  = threadIdx.x;
    int warp = tid >> 5, lane = tid & 31;
    int wm = (warp & 1) * 64;
    int wn = (warp >> 1) * 32;
    int ar = lane >> 2;
    int ac = lane & 3;

    float acc[16][4];
    #pragma unroll
    for (int i = 0; i < 16; i++)
        #pragma unroll
        for (int j = 0; j < 4; j++) acc[i][j] = 0.f;

    const float* WffC  = Wff  + (size_t)c * DD * NN;
    const float* WctxC = Wctx + (size_t)c * DD * NN;

    {
        #pragma unroll
        for (int i = 0; i < 2; i++) {
            int t = tid + i * 256;
            int m = t >> 2, kq = (t & 3) << 2;
            float4 v = *reinterpret_cast<const float4*>(x_in + (size_t)(m0 + m) * DD + kq);
            As[0][kq+0][m] = v.x; As[0][kq+1][m] = v.y;
            As[0][kq+2][m] = v.z; As[0][kq+3][m] = v.w;
        }
        #pragma unroll
        for (int i = 0; i < 2; i++) {
            int t = tid + i * 256;
            int kk = t >> 5, nq = (t & 31) << 2;
            *reinterpret_cast<float4*>(&Bs[0][kk][nq]) =
                *reinterpret_cast<const float4*>(WffC + (size_t)kk * NN + n0 + nq);
        }
    }
    __syncthreads();

    int cur = 0;
    for (int kt = 0; kt < K2 / BK; kt++) {
        float4 pa[2], pb[2];
        float  nscale = 1.0f;
        bool   has_next = (kt + 1 < K2 / BK);
        if (has_next) {
            int k0 = (kt + 1) * BK;
            const float* asrc = (k0 < DD) ? (x_in + k0) : (x_ctx + (k0 - DD));
            nscale = (k0 < DD) ? 1.0f : 0.3f;
            #pragma unroll
            for (int i = 0; i < 2; i++) {
                int t = tid + i * 256;
                int m = t >> 2, kq = (t & 3) << 2;
                pa[i] = *reinterpret_cast<const float4*>(asrc + (size_t)(m0 + m) * DD + kq);
            }
            const float* wsrc = (k0 < DD) ? (WffC + (size_t)k0 * NN)
                                          : (WctxC + (size_t)(k0 - DD) * NN);
            #pragma unroll
            for (int i = 0; i < 2; i++) {
                int t = tid + i * 256;
                int kk = t >> 5, nq = (t & 31) << 2;
                pb[i] = *reinterpret_cast<const float4*>(wsrc + (size_t)kk * NN + n0 + nq);
            }
        }

        #pragma unroll
        for (int kh = 0; kh < 2; kh++) {
            int kk0 = kh * 8;
            unsigned bh[8], bl[8];
            #pragma unroll
            for (int sn = 0; sn < 4; sn++) {
                float b0 = Bs[cur][kk0 + ac    ][wn + sn * 8 + ar];
                float b1 = Bs[cur][kk0 + ac + 4][wn + sn * 8 + ar];
                unsigned h0 = tf32_hi(b0), h1 = tf32_hi(b1);
                bh[sn*2+0] = h0; bh[sn*2+1] = h1;
                bl[sn*2+0] = __float_as_uint(b0 - __uint_as_float(h0));
                bl[sn*2+1] = __float_as_uint(b1 - __uint_as_float(h1));
            }
            #pragma unroll
            for (int sm = 0; sm < 4; sm++) {
                int mb = wm + sm * 16;
                float a0 = As[cur][kk0 + ac    ][mb + ar];
                float a1 = As[cur][kk0 + ac    ][mb + ar + 8];
                float a2 = As[cur][kk0 + ac + 4][mb + ar];
                float a3 = As[cur][kk0 + ac + 4][mb + ar + 8];
                unsigned ah0 = tf32_hi(a0), ah1 = tf32_hi(a1);
                unsigned ah2 = tf32_hi(a2), ah3 = tf32_hi(a3);
                unsigned al0 = __float_as_uint(a0 - __uint_as_float(ah0));
                unsigned al1 = __float_as_uint(a1 - __uint_as_float(ah1));
                unsigned al2 = __float_as_uint(a2 - __uint_as_float(ah2));
                unsigned al3 = __float_as_uint(a3 - __uint_as_float(ah3));
                #pragma unroll
                for (int sn = 0; sn < 4; sn++) {
                    float* cp = acc[sm * 4 + sn];
                    mma_tf32(cp[0], cp[1], cp[2], cp[3],
                             ah0, ah1, ah2, ah3, bh[sn*2], bh[sn*2+1]);
                    mma_tf32(cp[0], cp[1], cp[2], cp[3],
                             ah0, ah1, ah2, ah3, bl[sn*2], bl[sn*2+1]);
                    mma_tf32(cp[0], cp[1], cp[2], cp[3],
                             al0, al1, al2, al3, bh[sn*2], bh[sn*2+1]);
                }
            }
        }

        if (has_next) {
            int nxt = cur ^ 1;
            #pragma unroll
            for (int i = 0; i < 2; i++) {
                int t = tid + i * 256;
                int m = t >> 2, kq = (t & 3) << 2;
                As[nxt][kq+0][m] = pa[i].x * nscale;
                As[nxt][kq+1][m] = pa[i].y * nscale;
                As[nxt][kq+2][m] = pa[i].z * nscale;
                As[nxt][kq+3][m] = pa[i].w * nscale;
            }
            #pragma unroll
            for (int i = 0; i < 2; i++) {
                int t = tid + i * 256;
                int kk = t >> 5, nq = (t & 31) << 2;
                *reinterpret_cast<float4*>(&Bs[nxt][kk][nq]) = pb[i];
            }
            __syncthreads();
            cur = nxt;
        }
    }

    const float* bc = bias + (size_t)c * NN;
    #pragma unroll
    for (int sm = 0; sm < 4; sm++) {
        #pragma unroll
        for (int sn = 0; sn < 4; sn++) {
            const float* cp = acc[sm * 4 + sn];
            int col = n0 + wn + sn * 8 + ac * 2;
            float bx = bc[col], by = bc[col + 1];
            int r0 = m0 + wm + sm * 16 + ar;
            float2 v0 = make_float2(cp[0] + bx, cp[1] + by);
            float2 v1 = make_float2(cp[2] + bx, cp[3] + by);
            *reinterpret_cast<float2*>(act + ((size_t)r0 * CC + c) * NN + col)       = v0;
            *reinterpret_cast<float2*>(act + ((size_t)(r0 + 8) * CC + c) * NN + col) = v1;
        }
    }
}

// ---------------------------------------------------------------------------
// Kernel 2: warp-per-row k-WTA with margin-exact selection + normalize +
//           sparse pred/err.
// ---------------------------------------------------------------------------
__device__ __forceinline__ unsigned f2ord(float f) {
    unsigned u = __float_as_uint(f);
    return (u & 0x80000000u) ? ~u : (u | 0x80000000u);
}
__device__ __forceinline__ float ord2f(unsigned u) {
    unsigned v = (u & 0x80000000u) ? (u & 0x7FFFFFFFu) : ~u;
    return __uint_as_float(v);
}

__global__ __launch_bounds__(256) void topk_pred(
    const int* __restrict__ kptr, const float* __restrict__ x_in,
    const float* __restrict__ x_ctx,
    const float* __restrict__ Wff, const float* __restrict__ Wctx,
    const float* __restrict__ bias,
    const float* __restrict__ Wp,
    float* __restrict__ act, float* __restrict__ pred, float* __restrict__ err)
{
    int lane = threadIdx.x & 31;
    int w    = threadIdx.x >> 5;
    int row  = blockIdx.x * 8 + w;          // b*C + c
    int c = row & (CC - 1);
    int b = row >> 6;

    __shared__ float s_vv[8][64];
    __shared__ int   s_ii[8][64];
    __shared__ int   s_bi[8][32];     // borderline column indices
    __shared__ float s_be[8][32];     // borderline exact boosted values
    __shared__ int   s_bf[8][32];     // borderline selected flags

    const float4* arow = reinterpret_cast<const float4*>(act + (size_t)row * NN);
    const float4* brow = reinterpret_cast<const float4*>(g_boost + (size_t)c * NN);

    float    f[16];     // drive (approx)
    float    bf[16];    // boosted (approx)
    unsigned u[16];     // ordered bits of boosted
    #pragma unroll
    for (int i = 0; i < 4; i++) {
        float4 a  = arow[i * 32 + lane];
        float4 bo = brow[i * 32 + lane];
        f[i*4+0] = a.x; f[i*4+1] = a.y; f[i*4+2] = a.z; f[i*4+3] = a.w;
        bf[i*4+0] = a.x + bo.x; bf[i*4+1] = a.y + bo.y;
        bf[i*4+2] = a.z + bo.z; bf[i*4+3] = a.w + bo.w;
        #pragma unroll
        for (int q = 0; q < 4; q++) u[i*4+q] = f2ord(bf[i*4+q]);
    }

    int k = *kptr;

    // ---- binary search: T = k-th largest ordered value ----
    unsigned lmax = 0;
    #pragma unroll
    for (int s = 0; s < 16; s++) lmax = max(lmax, u[s]);
    unsigned mx = lmax, lb = lmax;
    #pragma unroll
    for (int o = 16; o; o >>= 1) {
        mx = max(mx, __shfl_xor_sync(0xffffffffu, mx, o));
        lb = min(lb, __shfl_xor_sync(0xffffffffu, lb, o));
    }
    if (k > 32) lb = 0u;

    unsigned diff = mx ^ lb;
    unsigned T;
    int topbit;
    if (diff == 0u) { T = mx; topbit = -1; }
    else {
        topbit = 31 - __clz(diff);
        unsigned mask = (topbit == 31) ? 0xFFFFFFFFu : ((2u << topbit) - 1u);
        T = mx & ~mask;
    }
    for (int bit = topbit; bit >= 0; --bit) {
        unsigned cand = T | (1u << bit);
        int cnt = 0;
        #pragma unroll
        for (int s = 0; s < 16; s++) cnt += (u[s] >= cand) ? 1 : 0;
        #pragma unroll
        for (int o = 16; o; o >>= 1) cnt += __shfl_xor_sync(0xffffffffu, cnt, o);
        if (cnt >= k) T = cand;
    }
    float Tf = ord2f(T);
    float thi = Tf + DELTA, tlo = Tf - DELTA;

    // ---- margin partition ----
    int nhi = 0, nbo = 0;
    #pragma unroll
    for (int s = 0; s < 16; s++) {
        nhi += (bf[s] > thi) ? 1 : 0;
        nbo += (bf[s] >= tlo && bf[s] <= thi) ? 1 : 0;
    }
    #pragma unroll
    for (int o = 16; o; o >>= 1) {
        nhi += __shfl_xor_sync(0xffffffffu, nhi, o);
        nbo += __shfl_xor_sync(0xffffffffu, nbo, o);
    }
    int r = k - nhi;            // winners still needed from borderline

    bool win[16];
    if (nbo == r || nbo > 32) {
        // unambiguous (or pathological overflow: fall back to approx compare)
        #pragma unroll
        for (int s = 0; s < 16; s++) win[s] = (bf[s] >= tlo);
        if (nbo > 32) {
            #pragma unroll
            for (int s = 0; s < 16; s++) win[s] = (u[s] >= T);
        }
    } else {
        // ---- rare path: exact fp32 recompute of borderline elements ----
        int bpos[16];
        int base = 0;
        #pragma unroll
        for (int i = 0; i < 4; i++) {
            #pragma unroll
            for (int q = 0; q < 4; q++) {
                int s = i * 4 + q;
                bool isb = (bf[s] >= tlo && bf[s] <= thi);
                unsigned m = __ballot_sync(0xffffffffu, isb);
                bpos[s] = -1;
                if (isb) {
                    int pos = base + __popc(m & ((1u << lane) - 1u));
                    bpos[s] = pos;
                    s_bi[w][pos] = i * 128 + lane * 4 + q;
                }
                base += __popc(m);
            }
        }
        __syncwarp();
        int mcnt = base;
        // exact dot for each borderline column, warp-cooperative
        const float* xi = x_in  + (size_t)b * DD;
        const float* xc = x_ctx + (size_t)b * DD;
        for (int e = 0; e < mcnt; e++) {
            int ncol = s_bi[w][e];
            const float* wf = Wff  + ((size_t)c * DD) * NN + ncol;
            const float* wc = Wctx + ((size_t)c * DD) * NN + ncol;
            float aff = 0.f, act2 = 0.f;
            #pragma unroll
            for (int t = 0; t < 8; t++) {
                int d = lane + t * 32;
                aff  = fmaf(xi[d], wf[(size_t)d * NN], aff);
                act2 = fmaf(xc[d], wc[(size_t)d * NN], act2);
            }
            #pragma unroll
            for (int o = 16; o; o >>= 1) {
                aff  += __shfl_xor_sync(0xffffffffu, aff,  o);
                act2 += __shfl_xor_sync(0xffffffffu, act2, o);
            }
            if (lane == 0)
                s_be[w][e] = aff + act2 * 0.3f + bias[(size_t)c * NN + ncol]
                           + g_boost[(size_t)c * NN + ncol];
            __syncwarp();
        }
        // exact rank among borderline: select if (#strictly greater) < r
        if (lane < mcnt) {
            float v = s_be[w][lane];
            int g = 0;
            for (int j = 0; j < mcnt; j++) g += (s_be[w][j] > v) ? 1 : 0;
            s_bf[w][lane] = (g < r) ? 1 : 0;
        }
        __syncwarp();
        #pragma unroll
        for (int s = 0; s < 16; s++) {
            bool isb = (bpos[s] >= 0);
            win[s] = (bf[s] > thi) || (isb && s_bf[w][bpos[s]]);
        }
    }

    // ---- normalization ----
    float lsum = 0.f;
    #pragma unroll
    for (int s = 0; s < 16; s++) {
        float rl = fmaxf(f[s], 0.f);
        lsum += win[s] ? rl : 0.f;
    }
    #pragma unroll
    for (int o = 16; o; o >>= 1) lsum += __shfl_xor_sync(0xffffffffu, lsum, o);
    float scale = (float)k / (lsum + 1e-8f);

    // ---- write act + compact nonzero winners ----
    float4* orow = reinterpret_cast<float4*>(act + (size_t)row * NN);
    int cnt_total = 0;
    #pragma unroll
    for (int i = 0; i < 4; i++) {
        float ov[4];
        #pragma unroll
        for (int q = 0; q < 4; q++) {
            int s = i * 4 + q;
            float rl  = fmaxf(f[s], 0.f);
            float val = win[s] ? rl * scale : 0.f;
            ov[q] = val;
            bool put = win[s] && (rl > 0.f);
            unsigned m = __ballot_sync(0xffffffffu, put);
            if (put) {
                int pos = cnt_total + __popc(m & ((1u << lane) - 1u));
                if (pos < 64) {
                    s_ii[w][pos] = i * 128 + lane * 4 + q;
                    s_vv[w][pos] = val;
                }
            }
            cnt_total += __popc(m);
        }
        orow[i * 32 + lane] = make_float4(ov[0], ov[1], ov[2], ov[3]);
    }
    if (cnt_total > 64) cnt_total = 64;
    __syncwarp();

    // ---- sparse prediction ----
    const float* WpC = Wp + (size_t)c * NN * DD;
    float4 acc0 = make_float4(0.f, 0.f, 0.f, 0.f);
    float4 acc1 = make_float4(0.f, 0.f, 0.f, 0.f);
    for (int j = 0; j < cnt_total; j++) {
        float vj = s_vv[w][j];
        const float4* wr = reinterpret_cast<const float4*>(WpC + (size_t)s_ii[w][j] * DD);
        float4 w0 = wr[lane];
        float4 w1 = wr[lane + 32];
        acc0.x = fmaf(vj, w0.x, acc0.x); acc0.y = fmaf(vj, w0.y, acc0.y);
        acc0.z = fmaf(vj, w0.z, acc0.z); acc0.w = fmaf(vj, w0.w, acc0.w);
        acc1.x = fmaf(vj, w1.x, acc1.x); acc1.y = fmaf(vj, w1.y, acc1.y);
        acc1.z = fmaf(vj, w1.z, acc1.z); acc1.w = fmaf(vj, w1.w, acc1.w);
    }

    const float4* xr = reinterpret_cast<const float4*>(x_in + (size_t)b * DD);
    float4 x0 = xr[lane], x1 = xr[lane + 32];
    float4* prow = reinterpret_cast<float4*>(pred + (size_t)row * DD);
    float4* erow = reinterpret_cast<float4*>(err  + (size_t)row * DD);
    prow[lane]      = acc0;
    prow[lane + 32] = acc1;
    erow[lane]      = make_float4(x0.x - acc0.x, x0.y - acc0.y, x0.z - acc0.z, x0.w - acc0.w);
    erow[lane + 32] = make_float4(x1.x - acc1.x, x1.y - acc1.y, x1.z - acc1.z, x1.w - acc1.w);
}

// ---------------------------------------------------------------------------
extern "C" void kernel_launch(void* const* d_in, const int* in_sizes, int n_in,
                              void* d_out, int out_size)
{
    const float* x_in  = (const float*)d_in[0];
    const float* x_ctx = (const float*)d_in[1];
    const float* Wff   = (const float*)d_in[2];
    const float* Wctx  = (const float*)d_in[3];
    const float* Wpred = (const float*)d_in[4];
    const float* bias  = (const float*)d_in[5];
    const float* avg   = (const float*)d_in[6];
    const int*   kptr  = (const int*)d_in[7];

    float* act  = (float*)d_out;                              // [B,C,N]
    float* pred = act  + (size_t)BB * CC * NN;                // [B,C,D]
    float* err  = pred + (size_t)BB * CC * DD;                // [B,C,D]

    boost_kernel<<<(CC * NN + 255) / 256, 256>>>(avg);

    dim3 g1(NN / 128, BB / 128, CC);
    drive_gemm<<<g1, 256>>>(x_in, x_ctx, Wff, Wctx, bias, act);

    topk_pred<<<BB * CC / 8, 256>>>(kptr, x_in, x_ctx, Wff, Wctx, bias,
                                    Wpred, act, pred, err);
}